// round 7
// baseline (speedup 1.0000x reference)
#include <cuda_runtime.h>
#include <math.h>

// MultiHeadAttention with exact 1.5-entmax across heads, fused single-pass.
// C=64, T=2048, E=512, H=8, d=64. 131072 tokens. Output fp32 [tok][512].
//
// R6 = R5 resubmit (R5 bench was an infra failure; kernel never ran):
// 512 threads/CTA (16 warps/SM), 2 e per thread in phase A, x staged
// pre-duplicated as fp32x2 pairs (broadcast LDS.128, no packing movs),
// K in [g][t][e] layout for conflict-free phase B, register-reuse phase C.

#define NTHREADS 512
#define TB 16
#define INV_SQRT_E 0.04419417382415922f   // 1/sqrt(512)

typedef unsigned long long u64;

// byte offsets in dynamic smem
#define OFF_W2 0            // u64[6144]: packed weights [proj][d*32+eg] = (W[2eg][d], W[2eg+1][d])
#define OFF_XD 49152        // u64[8192]: x duplicated (v,v), [row*64 + d]
#define OFF_B  114688       // float[192]
#define OFF_Q  115456       // float[128*66]       Q[row*66 + e]
#define OFF_K  149248       // float[8*16*66]      K[g*1056 + t*66 + e]
#define OFF_V  183040       // float[128*68]       V[row*68 + e]
#define OFF_A  217856       // float[128*9]        attn
#define SMEM_BYTES 222464

__device__ __forceinline__ void fma2(u64 &acc, u64 a, u64 b) {
    asm("fma.rn.f32x2 %0, %1, %2, %0;" : "+l"(acc) : "l"(a), "l"(b));
}
__device__ __forceinline__ u64 pack2(float lo, float hi) {
    u64 r; asm("mov.b64 %0, {%1, %2};" : "=l"(r) : "f"(lo), "f"(hi)); return r;
}
__device__ __forceinline__ void unpack2(u64 v, float &lo, float &hi) {
    asm("mov.b64 {%0, %1}, %2;" : "=f"(lo), "=f"(hi) : "l"(v));
}

__global__ __launch_bounds__(NTHREADS, 1)
void mha_entmax_kernel(const float* __restrict__ x,
                       const float* __restrict__ Wq, const float* __restrict__ bq,
                       const float* __restrict__ Wk, const float* __restrict__ bk,
                       const float* __restrict__ Wv, const float* __restrict__ bv,
                       float* __restrict__ out)
{
    extern __shared__ char smraw[];
    u64*   w2 = (u64*)(smraw + OFF_W2);
    u64*   xd = (u64*)(smraw + OFF_XD);
    float* sB = (float*)(smraw + OFF_B);
    float* sQ = (float*)(smraw + OFF_Q);
    float* sK = (float*)(smraw + OFF_K);
    float* sV = (float*)(smraw + OFF_V);
    float* sA = (float*)(smraw + OFF_A);

    const int tid = threadIdx.x;
    const int blk = blockIdx.x;

    // ---- stage packed weights: w2[p*2048 + d*32 + eg] = (W[2eg][d], W[2eg+1][d]) ----
    #pragma unroll
    for (int j = 0; j < 4; j++) {
        int idx = j * NTHREADS + tid;       // 0..2047
        int d = idx >> 5;
        int e = (idx & 31) * 2;
        w2[idx]        = pack2(Wq[e * 64 + d], Wq[(e + 1) * 64 + d]);
        w2[2048 + idx] = pack2(Wk[e * 64 + d], Wk[(e + 1) * 64 + d]);
        w2[4096 + idx] = pack2(Wv[e * 64 + d], Wv[(e + 1) * 64 + d]);
    }
    if (tid < 64) { sB[tid] = bq[tid]; sB[64 + tid] = bk[tid]; sB[128 + tid] = bv[tid]; }

    // ---- stage x duplicated: xd[row*64 + d] = (x,x); coalesced LDG.64 + contiguous STS.128 ----
    {
        const float2* gx2 = (const float2*)(x + (size_t)blk * (TB * 512));
        #pragma unroll
        for (int j = 0; j < 8; j++) {
            int idx2 = j * NTHREADS + tid;  // 0..4095, float2 index
            float2 v = gx2[idx2];
            ulonglong2 dup;
            dup.x = pack2(v.x, v.x);
            dup.y = pack2(v.y, v.y);
            *(ulonglong2*)(xd + idx2 * 2) = dup;
        }
    }
    __syncthreads();

    // ================= Phase A: projections (fp32x2 GEMM) =================
    // thread -> token rg (8 rows), e-pair eg (e = 2eg..2eg+1), all 3 projections.
    const int rg = tid >> 5;                // 0..15 (warp-uniform: one warp = one token)
    const int eg = tid & 31;

    u64 aq[8], ak[8], av[8];
    {
        u64 b0 = pack2(sB[2 * eg],       sB[2 * eg + 1]);
        u64 b1 = pack2(sB[64 + 2 * eg],  sB[64 + 2 * eg + 1]);
        u64 b2 = pack2(sB[128 + 2 * eg], sB[128 + 2 * eg + 1]);
        #pragma unroll
        for (int i = 0; i < 8; i++) { aq[i] = b0; ak[i] = b1; av[i] = b2; }
    }

    const u64* wq = w2 + eg;
    const u64* wk = w2 + 2048 + eg;
    const u64* wv = w2 + 4096 + eg;
    const u64* xb = xd + rg * (8 * 64);

    #pragma unroll 2
    for (int d = 0; d < 64; d += 2) {
        u64 wq0 = wq[d * 32], wq1 = wq[d * 32 + 32];
        u64 wk0 = wk[d * 32], wk1 = wk[d * 32 + 32];
        u64 wv0 = wv[d * 32], wv1 = wv[d * 32 + 32];
        #pragma unroll
        for (int i = 0; i < 8; i++) {
            ulonglong2 xx = *(const ulonglong2*)(xb + i * 64 + d);  // broadcast LDS.128
            fma2(aq[i], xx.x, wq0); fma2(ak[i], xx.x, wk0); fma2(av[i], xx.x, wv0);
            fma2(aq[i], xx.y, wq1); fma2(ak[i], xx.y, wk1); fma2(av[i], xx.y, wv1);
        }
    }

    // epilogue: contiguous conflict-free STS.64 of packed accumulators
    #pragma unroll
    for (int i = 0; i < 8; i++) {
        int row = rg * 8 + i;
        *(u64*)&sQ[row * 66 + 2 * eg]              = aq[i];
        *(u64*)&sK[i * 1056 + rg * 66 + 2 * eg]    = ak[i];   // K[g=i][t=rg][e]
        *(u64*)&sV[row * 68 + 2 * eg]              = av[i];
    }
    __syncthreads();

    // ================= Phase B: scores + exact entmax15 =================
    if (tid < 128) {
        const int t = tid >> 3;              // token in tile

        // q row into registers as fp32x2 pairs
        const float* qrow = sQ + tid * 66;
        u64 q2[32];
        #pragma unroll
        for (int ep = 0; ep < 32; ep++) q2[ep] = *(const u64*)(qrow + 2 * ep);

        // packed dot products against 8 k rows (conflict-free broadcast LDS.64)
        u64 acc2[8];
        #pragma unroll
        for (int g = 0; g < 8; g++) acc2[g] = 0ULL;
        const float* kb = sK + t * 66;
        #pragma unroll 4
        for (int ep = 0; ep < 32; ep++) {
            u64 qv = q2[ep];
            #pragma unroll
            for (int g = 0; g < 8; g++) {
                u64 kv = *(const u64*)(kb + g * 1056 + 2 * ep);
                fma2(acc2[g], qv, kv);
            }
        }
        float s[8];
        #pragma unroll
        for (int g = 0; g < 8; g++) {
            float lo, hi; unpack2(acc2[g], lo, hi);
            s[g] = (lo + hi) * INV_SQRT_E;
        }

        // entmax15: x = (s - max)/2
        float m = s[0];
        #pragma unroll
        for (int g = 1; g < 8; g++) m = fmaxf(m, s[g]);
        float xv[8], xs[8];
        #pragma unroll
        for (int g = 0; g < 8; g++) { xv[g] = (s[g] - m) * 0.5f; xs[g] = xv[g]; }

        // Batcher odd-even mergesort, 19 comparators, descending
        #define CE(A, B) { if (xs[A] < xs[B]) { float _t = xs[A]; xs[A] = xs[B]; xs[B] = _t; } }
        CE(0,1) CE(2,3) CE(4,5) CE(6,7)
        CE(0,2) CE(1,3) CE(4,6) CE(5,7)
        CE(1,2) CE(5,6)
        CE(0,4) CE(1,5) CE(2,6) CE(3,7)
        CE(2,4) CE(3,5)
        CE(1,2) CE(3,4) CE(5,6)
        #undef CE

        // pass 1: support count (matches reference's sum(tau <= xs))
        int cnt = 0;
        {
            float cs = 0.0f, css = 0.0f;
            #pragma unroll
            for (int i = 0; i < 8; i++) {
                cs += xs[i]; css += xs[i] * xs[i];
                float rho = (float)(i + 1);
                float mean = cs / rho, msq = css / rho;
                float ss = rho * (msq - mean * mean);
                float delta = (1.0f - ss) / rho;
                float sq = (delta > 0.0f) ? sqrtf(delta) : 0.0f;
                float tau = mean - sq;
                if (tau <= xs[i]) cnt++;
            }
        }
        // pass 2: tau_star = tau[cnt-1]
        float tau_star = 0.0f;
        {
            float cs = 0.0f, css = 0.0f;
            #pragma unroll
            for (int i = 0; i < 8; i++) {
                cs += xs[i]; css += xs[i] * xs[i];
                float rho = (float)(i + 1);
                float mean = cs / rho, msq = css / rho;
                float ss = rho * (msq - mean * mean);
                float delta = (1.0f - ss) / rho;
                float sq = (delta > 0.0f) ? sqrtf(delta) : 0.0f;
                float tau = mean - sq;
                if (i == cnt - 1) tau_star = tau;
            }
        }

        float* arow = sA + tid * 9;
        #pragma unroll
        for (int g = 0; g < 8; g++) {
            float y = fmaxf(xv[g] - tau_star, 0.0f);
            arow[g] = y * y;
        }
    }
    __syncthreads();

    // ================= Phase C: out = attn @ v (V float4s reused across 8 heads) =================
    if (tid < 256) {
        const int t  = tid >> 4;             // token
        const int d4 = tid & 15;             // float4 column

        const float* ar = sA + t * 72;       // 8 attn rows, stride 9
        float a[64];
        #pragma unroll
        for (int h = 0; h < 8; h++)
            #pragma unroll
            for (int g = 0; g < 8; g++)
                a[h * 8 + g] = ar[h * 9 + g];

        const float* vb = sV + t * 544 + d4 * 4;
        float4 vr[8];
        #pragma unroll
        for (int g = 0; g < 8; g++) vr[g] = *(const float4*)(vb + g * 68);

        float* gout = out + (size_t)blk * (TB * 512) + (size_t)t * 512 + d4 * 4;
        #pragma unroll
        for (int h = 0; h < 8; h++) {
            float4 o = make_float4(0.f, 0.f, 0.f, 0.f);
            #pragma unroll
            for (int g = 0; g < 8; g++) {
                float av_ = a[h * 8 + g];
                o.x += av_ * vr[g].x;
                o.y += av_ * vr[g].y;
                o.z += av_ * vr[g].z;
                o.w += av_ * vr[g].w;
            }
            *(float4*)(gout + h * 64) = o;   // 16 lanes x 16B contiguous per (t,h)
        }
    }
}

extern "C" void kernel_launch(void* const* d_in, const int* in_sizes, int n_in,
                              void* d_out, int out_size) {
    const float* x  = (const float*)d_in[0];
    const float* Wq = (const float*)d_in[1];
    const float* bq = (const float*)d_in[2];
    const float* Wk = (const float*)d_in[3];
    const float* bk = (const float*)d_in[4];
    const float* Wv = (const float*)d_in[5];
    const float* bv = (const float*)d_in[6];
    float* out = (float*)d_out;

    int ntok = in_sizes[0] / 512;          // 131072
    int blocks = ntok / TB;                // 8192

    cudaFuncSetAttribute(mha_entmax_kernel,
                         cudaFuncAttributeMaxDynamicSharedMemorySize, SMEM_BYTES);
    mha_entmax_kernel<<<blocks, NTHREADS, SMEM_BYTES>>>(x, Wq, bq, Wk, bk, Wv, bv, out);
}